// round 10
// baseline (speedup 1.0000x reference)
#include <cuda_runtime.h>
#include <cstdint>
#include <math.h>

#define D    128
#define S_MAX 125000
#define EPS  1e-13f

// Scratch (static device globals -- no allocation)
__device__ float g_y[(size_t)S_MAX * D];   // 64 MB: per-segment normalized weighted sum of x
__device__ float g_sg[S_MAX];              // per-segment gate sum
__device__ int   g_starts[S_MAX + 1];      // segment start offsets

// ---------------------------------------------------------------------------
// Kernel 1: segment start offsets from the sorted index array (int4 scan).
// ---------------------------------------------------------------------------
__global__ void seg_starts_kernel(const int* __restrict__ idx, int N, int S) {
    int t  = blockIdx.x * blockDim.x + threadIdx.x;
    int n0 = t * 4;
    if (n0 >= N) return;

    int v0, v1, v2, v3;
    if (n0 + 3 < N) {
        int4 c = *(const int4*)(idx + n0);
        v0 = c.x; v1 = c.y; v2 = c.z; v3 = c.w;
    } else {
        v0 = idx[n0];
        v1 = (n0 + 1 < N) ? idx[n0 + 1] : v0;
        v2 = (n0 + 2 < N) ? idx[n0 + 2] : v1;
        v3 = (n0 + 3 < N) ? idx[n0 + 3] : v2;
    }
    int prev = (n0 == 0) ? -1 : idx[n0 - 1];

    int vals[4] = {v0, v1, v2, v3};
    #pragma unroll
    for (int j = 0; j < 4; ++j) {
        if (n0 + j < N) {
            int cur = vals[j];
            for (int s = prev + 1; s <= cur; ++s) g_starts[s] = n0 + j;
            prev = cur;
        }
    }
    if (n0 + 4 >= N) {
        for (int s = prev + 1; s <= S; ++s) g_starts[s] = N;
    }
}

__device__ __forceinline__ float dot4(float4 a, float4 b) {
    return a.x * b.x + a.y * b.y + a.z * b.z + a.w * b.w;
}

// ---------------------------------------------------------------------------
// Kernel 2: single-pass fused gate + weighted segment aggregation,
// SOFTWARE-PIPELINED: batch i+1's 4 row-loads are issued BEFORE batch i's
// shuffle-reduce chain, doubling loads-in-flight (~5 -> ~9) while keeping a
// single reduce chain and ~50 registers.
// Balanced work split: fixed grid, each warp sweeps ~14 contiguous segments.
// ---------------------------------------------------------------------------
#define AGG_BLOCKS 1184   // 148 SMs x 8 blocks
#define AGG_WARPS  (AGG_BLOCKS * 8)

__global__ void __launch_bounds__(256)
agg_kernel(const float* __restrict__ x,
           const float* __restrict__ w,
           const float* __restrict__ Wg,
           const float* __restrict__ bgp,
           int S) {
    int gw   = (int)((blockIdx.x * (unsigned)blockDim.x + threadIdx.x) >> 5);
    int lane = threadIdx.x & 31;
    int q    = lane >> 3;
    int pm1 = q ^ 1, pm2 = q ^ 2, pm3 = q ^ 3;

    int per = (S + AGG_WARPS - 1) / AGG_WARPS;
    int s0  = gw * per;
    int s1  = s0 + per; if (s1 > S) s1 = S;
    if (s0 >= s1) return;

    float4 wg  = *(const float4*)(Wg + lane * 4);
    float  bg0 = bgp[0];

    int r0 = g_starts[s0];
    for (int s = s0; s < s1; ++s) {
        int r1  = g_starts[s + 1];
        int len = r1 - r0;
        const float* xb = x + (size_t)r0 * D + lane * 4;

        float4 acc = make_float4(0.f, 0.f, 0.f, 0.f);
        float  denom = 0.f;
        float4 z = make_float4(0.f, 0.f, 0.f, 0.f);

        // ---- prologue: load batch 0 ----
        float4 c0 = z, c1 = z, c2 = z, c3 = z;
        {
            int rA = q, rB = pm1, rC = pm2, rD = pm3;
            if (rA < len) c0 = *(const float4*)(xb + (size_t)rA * D);
            if (rB < len) c1 = *(const float4*)(xb + (size_t)rB * D);
            if (rC < len) c2 = *(const float4*)(xb + (size_t)rC * D);
            if (rD < len) c3 = *(const float4*)(xb + (size_t)rD * D);
        }
        float wc = (q < len) ? w[r0 + q] : 0.f;

        for (int base = 0; base < len; base += 4) {
            // ---- prefetch batch base+4 (issues before the reduce chain) ----
            float4 n0 = z, n1 = z, n2 = z, n3 = z;
            float  wn = 0.f;
            {
                int rA = base + 4 + q;
                int rB = base + 4 + pm1;
                int rC = base + 4 + pm2;
                int rD = base + 4 + pm3;
                if (rA < len) { n0 = *(const float4*)(xb + (size_t)rA * D); wn = w[r0 + rA]; }
                if (rB < len) n1 = *(const float4*)(xb + (size_t)rB * D);
                if (rC < len) n2 = *(const float4*)(xb + (size_t)rC * D);
                if (rD < len) n3 = *(const float4*)(xb + (size_t)rD * D);
            }

            // ---- compute on current batch ----
            float p0 = dot4(c0, wg);
            float p1 = dot4(c1, wg);
            float p2 = dot4(c2, wg);
            float p3 = dot4(c3, wg);

            float t01 = p0 + __shfl_xor_sync(0xffffffffu, p1, 8);
            float t23 = p2 + __shfl_xor_sync(0xffffffffu, p3, 8);
            float t   = t01 + __shfl_xor_sync(0xffffffffu, t23, 16);
            t += __shfl_xor_sync(0xffffffffu, t, 1);
            t += __shfl_xor_sync(0xffffffffu, t, 2);
            t += __shfl_xor_sync(0xffffffffu, t, 4);

            float g = wc * __expf(t + bg0);
            denom += g;

            float g1 = __shfl_xor_sync(0xffffffffu, g, 8);
            float g2 = __shfl_xor_sync(0xffffffffu, g, 16);
            float g3 = __shfl_xor_sync(0xffffffffu, g, 24);

            acc.x += g * c0.x + g1 * c1.x + g2 * c2.x + g3 * c3.x;
            acc.y += g * c0.y + g1 * c1.y + g2 * c2.y + g3 * c3.y;
            acc.z += g * c0.z + g1 * c1.z + g2 * c2.z + g3 * c3.z;
            acc.w += g * c0.w + g1 * c1.w + g2 * c2.w + g3 * c3.w;

            // ---- rotate pipeline ----
            c0 = n0; c1 = n1; c2 = n2; c3 = n3; wc = wn;
        }

        denom += __shfl_xor_sync(0xffffffffu, denom, 8);
        denom += __shfl_xor_sync(0xffffffffu, denom, 16);

        float inv = 1.f / (denom + EPS);
        float4 o;
        o.x = acc.x * inv; o.y = acc.y * inv;
        o.z = acc.z * inv; o.w = acc.w * inv;
        *(float4*)(g_y + (size_t)s * D + lane * 4) = o;
        if (lane == 0) g_sg[s] = denom * inv;

        r0 = r1;
    }
}

// ---------------------------------------------------------------------------
// Kernel 3: out[S,128] = y @ Wm + sg (x) bm   (tf32 mma.sync, fp32 accum)
// EXACT R6 version (record holder): float smem, cvt in mainloop.
// ---------------------------------------------------------------------------
#define BM 128
#define BN 128
#define BK 32

__device__ __forceinline__ uint32_t f2tf32(float f) {
    uint32_t r;
    asm("cvt.rna.tf32.f32 %0, %1;" : "=r"(r) : "f"(f));
    return r;
}

__device__ __forceinline__ void mma_tf32(float* c, const uint32_t* a, const uint32_t* b) {
    asm volatile(
        "mma.sync.aligned.m16n8k8.row.col.f32.tf32.tf32.f32 "
        "{%0,%1,%2,%3}, {%4,%5,%6,%7}, {%8,%9}, {%0,%1,%2,%3};\n"
        : "+f"(c[0]), "+f"(c[1]), "+f"(c[2]), "+f"(c[3])
        : "r"(a[0]), "r"(a[1]), "r"(a[2]), "r"(a[3]), "r"(b[0]), "r"(b[1]));
}

__global__ void __launch_bounds__(256)
gemm_kernel(const float* __restrict__ Wm,
            const float* __restrict__ bm,
            float* __restrict__ out, int S) {
    __shared__ float yS[BM][BK + 4];
    __shared__ float wS[BK][BN + 4];

    int tid  = threadIdx.x;
    int wid  = tid >> 5;
    int lane = tid & 31;
    int warp_m = wid & 3;
    int warp_n = wid >> 2;
    int grp = lane >> 2;
    int tg  = lane & 3;
    int rowbase = blockIdx.x * BM;

    float c[2][8][4];
    #pragma unroll
    for (int mf = 0; mf < 2; ++mf)
        #pragma unroll
        for (int nf = 0; nf < 8; ++nf)
            #pragma unroll
            for (int i = 0; i < 4; ++i) c[mf][nf][i] = 0.f;

    for (int kt = 0; kt < D; kt += BK) {
        __syncthreads();
        {
            int r = tid >> 3;
            int qq = tid & 7;
            #pragma unroll
            for (int it = 0; it < 4; ++it) {
                int row  = r + it * 32;
                int grow = rowbase + row;
                float4 v = make_float4(0.f,0.f,0.f,0.f);
                if (grow < S)
                    v = *(const float4*)(g_y + (size_t)grow * D + kt + qq * 4);
                *(float4*)&yS[row][qq * 4] = v;
            }
            int k = tid >> 3;
            #pragma unroll
            for (int it = 0; it < 4; ++it) {
                int q2 = (tid & 7) + it * 8;
                *(float4*)&wS[k][q2 * 4] =
                    *(const float4*)(Wm + (size_t)(kt + k) * D + q2 * 4);
            }
        }
        __syncthreads();

        #pragma unroll
        for (int ks = 0; ks < BK; ks += 8) {
            uint32_t a[2][4];
            uint32_t b[8][2];
            #pragma unroll
            for (int mf = 0; mf < 2; ++mf) {
                int r = warp_m * 32 + mf * 16;
                a[mf][0] = f2tf32(yS[r + grp    ][ks + tg    ]);
                a[mf][1] = f2tf32(yS[r + grp + 8][ks + tg    ]);
                a[mf][2] = f2tf32(yS[r + grp    ][ks + tg + 4]);
                a[mf][3] = f2tf32(yS[r + grp + 8][ks + tg + 4]);
            }
            #pragma unroll
            for (int nf = 0; nf < 8; ++nf) {
                int col = warp_n * 64 + nf * 8 + grp;
                b[nf][0] = f2tf32(wS[ks + tg    ][col]);
                b[nf][1] = f2tf32(wS[ks + tg + 4][col]);
            }
            #pragma unroll
            for (int mf = 0; mf < 2; ++mf)
                #pragma unroll
                for (int nf = 0; nf < 8; ++nf)
                    mma_tf32(c[mf][nf], a[mf], b[nf]);
        }
    }

    #pragma unroll
    for (int mf = 0; mf < 2; ++mf) {
        int row0 = rowbase + warp_m * 32 + mf * 16 + grp;
        int row1 = row0 + 8;
        float sgA = (row0 < S) ? g_sg[row0] : 0.f;
        float sgB = (row1 < S) ? g_sg[row1] : 0.f;
        #pragma unroll
        for (int nf = 0; nf < 8; ++nf) {
            int col = warp_n * 64 + nf * 8 + tg * 2;
            float b0 = bm[col], b1 = bm[col + 1];
            if (row0 < S) {
                float2 o;
                o.x = c[mf][nf][0] + sgA * b0;
                o.y = c[mf][nf][1] + sgA * b1;
                *(float2*)(out + (size_t)row0 * D + col) = o;
            }
            if (row1 < S) {
                float2 o;
                o.x = c[mf][nf][2] + sgB * b0;
                o.y = c[mf][nf][3] + sgB * b1;
                *(float2*)(out + (size_t)row1 * D + col) = o;
            }
        }
    }
}

// ---------------------------------------------------------------------------
extern "C" void kernel_launch(void* const* d_in, const int* in_sizes, int n_in,
                              void* d_out, int out_size) {
    const float* x   = (const float*)d_in[0];
    const int*   idx = (const int*)  d_in[1];
    const float* w   = (const float*)d_in[2];
    const float* Wg  = (const float*)d_in[3];
    const float* bg  = (const float*)d_in[4];
    const float* Wm  = (const float*)d_in[5];
    const float* bm  = (const float*)d_in[6];
    float* out = (float*)d_out;

    int N = in_sizes[1];
    int S = out_size / D;

    int quads = (N + 3) / 4;
    seg_starts_kernel<<<(quads + 255) / 256, 256>>>(idx, N, S);

    agg_kernel<<<AGG_BLOCKS, 256>>>(x, w, Wg, bg, S);

    gemm_kernel<<<(S + BM - 1) / BM, 256>>>(Wm, bm, out, S);
}